// round 15
// baseline (speedup 1.0000x reference)
#include <cuda_runtime.h>
#include <cuda_bf16.h>
#include <cuda_fp16.h>

#define N_NODES 100000
#define DIM 128
#define MAX_EDGES 1700000
#define SCAN_CHUNK 512
#define N_CHUNKS ((N_NODES + SCAN_CHUNK - 1) / SCAN_CHUNK)   // 196

// ---------------------------------------------------------------------------
// Scratch (allocation-free rule: device globals)
// ---------------------------------------------------------------------------
__device__ __half g_h[N_NODES * DIM];         // h = x @ W^T  (fp16)
__device__ __half g_Wh[DIM * DIM];            // W in fp16
__device__ int    g_cnt[N_NODES];             // per-row count; self-restored to 0 by rowgather
__device__ int    g_rowstart[N_NODES + 1];    // CSR offsets
__device__ int    g_blocksum[N_CHUNKS];       // per-chunk totals
__device__ int    g_rank[MAX_EDGES];          // edge rank within its row (from hist)
__device__ int2   g_edge[MAX_EDGES];          // (col, val-bits) grouped by row

// ---------------------------------------------------------------------------
__global__ void k_prep_w(const float* __restrict__ W) {
    int idx = blockIdx.x * blockDim.x + threadIdx.x;
    if (idx < DIM * DIM) g_Wh[idx] = __float2half_rn(W[idx]);
}

// ---------------------------------------------------------------------------
// GEMM via HMMA (unchanged — proven; fully hidden under LTS-bound binning)
// ---------------------------------------------------------------------------
#define SSTRIDE 136

__global__ void __launch_bounds__(256) k_gemm(const float* __restrict__ x) {
    __shared__ __half sA[32 * SSTRIDE];
    __shared__ __half sB[DIM * SSTRIDE];

    const int tid  = threadIdx.x;
    const int row0 = blockIdx.x * 32;

    const uint4* w4 = reinterpret_cast<const uint4*>(g_Wh);
    #pragma unroll
    for (int i = tid; i < 2048; i += 256) {
        int r = i >> 4, cg = i & 15;
        *reinterpret_cast<uint4*>(&sB[r * SSTRIDE + cg * 8]) = w4[i];
    }
    const float4* x4 = reinterpret_cast<const float4*>(x + (size_t)row0 * DIM);
    #pragma unroll
    for (int i = tid; i < 1024; i += 256) {
        float4 v = x4[i];
        int r = i >> 5, k4 = i & 31;
        __half2 p0 = __floats2half2_rn(v.x, v.y);
        __half2 p1 = __floats2half2_rn(v.z, v.w);
        __half* d = &sA[r * SSTRIDE + k4 * 4];
        *reinterpret_cast<__half2*>(d)     = p0;
        *reinterpret_cast<__half2*>(d + 2) = p1;
    }
    __syncthreads();

    const int warp = tid >> 5, lane = tid & 31;
    const int wr = (warp & 1) * 16;
    const int wc = (warp >> 1) * 32;
    const int qr = lane >> 2, qc = lane & 3;

    float c[4][4];
    #pragma unroll
    for (int nc = 0; nc < 4; nc++)
        #pragma unroll
        for (int j = 0; j < 4; j++) c[nc][j] = 0.f;

    #pragma unroll
    for (int ks = 0; ks < 8; ks++) {
        const int k0 = ks * 16 + qc * 2;
        const __half* A0 = &sA[(wr + qr) * SSTRIDE + k0];
        const __half* A8 = A0 + 8 * SSTRIDE;
        unsigned a0 = *reinterpret_cast<const unsigned*>(A0);
        unsigned a1 = *reinterpret_cast<const unsigned*>(A8);
        unsigned a2 = *reinterpret_cast<const unsigned*>(A0 + 8);
        unsigned a3 = *reinterpret_cast<const unsigned*>(A8 + 8);
        #pragma unroll
        for (int nc = 0; nc < 4; nc++) {
            const int n = wc + nc * 8 + qr;
            const __half* B0 = &sB[n * SSTRIDE + k0];
            unsigned b0 = *reinterpret_cast<const unsigned*>(B0);
            unsigned b1 = *reinterpret_cast<const unsigned*>(B0 + 8);
            asm("mma.sync.aligned.m16n8k16.row.col.f32.f16.f16.f32 "
                "{%0,%1,%2,%3}, {%4,%5,%6,%7}, {%8,%9}, {%0,%1,%2,%3};"
                : "+f"(c[nc][0]), "+f"(c[nc][1]), "+f"(c[nc][2]), "+f"(c[nc][3])
                : "r"(a0), "r"(a1), "r"(a2), "r"(a3), "r"(b0), "r"(b1));
        }
    }

    const int r0g = row0 + wr + qr;
    #pragma unroll
    for (int nc = 0; nc < 4; nc++) {
        const int col = wc + nc * 8 + qc * 2;
        __half2 lo = __floats2half2_rn(c[nc][0], c[nc][1]);
        __half2 hi = __floats2half2_rn(c[nc][2], c[nc][3]);
        *reinterpret_cast<__half2*>(&g_h[(size_t)r0g * DIM + col])       = lo;
        *reinterpret_cast<__half2*>(&g_h[(size_t)(r0g + 8) * DIM + col]) = hi;
    }
}

// ---------------------------------------------------------------------------
// Phase 1: histogram + RANK RECORDING. The atomicAdd's return value is each
// edge's rank within its row — store it so place needs no atomics.
// g_cnt arrives zeroed (BSS init first call; rowgather restores after use).
// ---------------------------------------------------------------------------
__global__ void k_hist(const int* __restrict__ erow, int n_edges) {
    int t  = blockIdx.x * blockDim.x + threadIdx.x;
    int e4 = n_edges >> 2;
    if (t < e4) {
        int4 r = reinterpret_cast<const int4*>(erow)[t];
        int4 k;
        k.x = atomicAdd(&g_cnt[r.x], 1);
        k.y = atomicAdd(&g_cnt[r.y], 1);
        k.z = atomicAdd(&g_cnt[r.z], 1);
        k.w = atomicAdd(&g_cnt[r.w], 1);
        reinterpret_cast<int4*>(g_rank)[t] = k;
    } else {
        int e = e4 * 4 + (t - e4);
        if (e < n_edges) g_rank[e] = atomicAdd(&g_cnt[erow[e]], 1);
    }
}

// ---------------------------------------------------------------------------
// Phase 2a: per-chunk exclusive scan; writes per-chunk totals. (proven)
// ---------------------------------------------------------------------------
__global__ void __launch_bounds__(SCAN_CHUNK) k_scan1() {
    __shared__ int wsum[SCAN_CHUNK / 32];
    int tid  = threadIdx.x;
    int gidx = blockIdx.x * SCAN_CHUNK + tid;
    int v    = (gidx < N_NODES) ? g_cnt[gidx] : 0;

    int lane = tid & 31, wid = tid >> 5;
    int incl = v;
    #pragma unroll
    for (int d = 1; d < 32; d <<= 1) {
        int t = __shfl_up_sync(0xffffffff, incl, d);
        if (lane >= d) incl += t;
    }
    if (lane == 31) wsum[wid] = incl;
    __syncthreads();
    if (wid == 0) {
        int w = (lane < SCAN_CHUNK / 32) ? wsum[lane] : 0;
        int wi = w;
        #pragma unroll
        for (int d = 1; d < 32; d <<= 1) {
            int t = __shfl_up_sync(0xffffffff, wi, d);
            if (lane >= d) wi += t;
        }
        if (lane < SCAN_CHUNK / 32) wsum[lane] = wi - w;
    }
    __syncthreads();
    int excl = incl - v + wsum[wid];
    if (gidx < N_NODES) g_cnt[gidx] = excl;
    if (tid == SCAN_CHUNK - 1) g_blocksum[blockIdx.x] = excl + v;
}

// ---------------------------------------------------------------------------
// Phase 2b: merged chunk-prefix + rowstart write. (proven R14)
// ---------------------------------------------------------------------------
__global__ void __launch_bounds__(SCAN_CHUNK) k_scanC(int n_edges) {
    __shared__ int s_prefix;
    const int tid = threadIdx.x;
    const int bid = blockIdx.x;

    if (tid < 32) {
        int acc = 0;
        for (int j = tid; j < bid; j += 32) acc += g_blocksum[j];
        #pragma unroll
        for (int d = 16; d; d >>= 1)
            acc += __shfl_down_sync(0xffffffff, acc, d);
        if (tid == 0) s_prefix = acc;
    }
    __syncthreads();

    int gidx = bid * SCAN_CHUNK + tid;
    if (gidx < N_NODES) g_rowstart[gidx] = g_cnt[gidx] + s_prefix;
    if (gidx == N_NODES - 1) g_rowstart[N_NODES] = n_edges;
}

// ---------------------------------------------------------------------------
// Phase 3: ATOMIC-FREE place — pos = rowstart[row] + rank[edge].
// ---------------------------------------------------------------------------
__global__ void k_place(const int*   __restrict__ erow,
                        const int*   __restrict__ ecol,
                        const float* __restrict__ eval,
                        int n_edges) {
    int t  = blockIdx.x * blockDim.x + threadIdx.x;
    int e4 = n_edges >> 2;
    if (t < e4) {
        int4   r = reinterpret_cast<const int4*>(erow)[t];
        int4   c = reinterpret_cast<const int4*>(ecol)[t];
        float4 v = reinterpret_cast<const float4*>(eval)[t];
        int4   k = reinterpret_cast<const int4*>(g_rank)[t];
        g_edge[__ldg(&g_rowstart[r.x]) + k.x] = make_int2(c.x, __float_as_int(v.x));
        g_edge[__ldg(&g_rowstart[r.y]) + k.y] = make_int2(c.y, __float_as_int(v.y));
        g_edge[__ldg(&g_rowstart[r.z]) + k.z] = make_int2(c.z, __float_as_int(v.z));
        g_edge[__ldg(&g_rowstart[r.w]) + k.w] = make_int2(c.w, __float_as_int(v.w));
    } else {
        int e = e4 * 4 + (t - e4);
        if (e < n_edges) {
            g_edge[__ldg(&g_rowstart[erow[e]]) + g_rank[e]] =
                make_int2(ecol[e], __float_as_int(eval[e]));
        }
    }
}

// ---------------------------------------------------------------------------
// Phase 4: rowgather (proven) + self-restoring counter zero.
// ---------------------------------------------------------------------------
__device__ __forceinline__ void acc_edge16(float4& aLo, float4& aHi, uint4 p, float v) {
    float2 f0 = __half22float2(*reinterpret_cast<__half2*>(&p.x));
    float2 f1 = __half22float2(*reinterpret_cast<__half2*>(&p.y));
    float2 f2 = __half22float2(*reinterpret_cast<__half2*>(&p.z));
    float2 f3 = __half22float2(*reinterpret_cast<__half2*>(&p.w));
    aLo.x += v * f0.x; aLo.y += v * f0.y; aLo.z += v * f1.x; aLo.w += v * f1.y;
    aHi.x += v * f2.x; aHi.y += v * f2.y; aHi.z += v * f3.x; aHi.w += v * f3.y;
}

__global__ void __launch_bounds__(128) k_rowgather(float* __restrict__ out) {
    int grp = blockIdx.x * 8 + (threadIdx.x >> 4);
    int sl  = threadIdx.x & 15;
    if (grp >= N_NODES) return;

    int beg = __ldg(&g_rowstart[grp]);
    int end = __ldg(&g_rowstart[grp + 1]);

    // Self-restore: leave g_cnt zeroed for the next graph replay's hist.
    if (sl == 0) g_cnt[grp] = 0;

    const uint4* hh = reinterpret_cast<const uint4*>(g_h);

    float4 l0 = make_float4(0.f,0.f,0.f,0.f), h0 = make_float4(0.f,0.f,0.f,0.f);
    float4 l1 = make_float4(0.f,0.f,0.f,0.f), h1 = make_float4(0.f,0.f,0.f,0.f);

    int i = beg;
    for (; i + 8 <= end; i += 8) {
        int2 e0 = g_edge[i + 0];
        int2 e1 = g_edge[i + 1];
        int2 e2 = g_edge[i + 2];
        int2 e3 = g_edge[i + 3];
        int2 e4 = g_edge[i + 4];
        int2 e5 = g_edge[i + 5];
        int2 e6 = g_edge[i + 6];
        int2 e7 = g_edge[i + 7];
        uint4 p0 = hh[(size_t)e0.x * 16 + sl];
        uint4 p1 = hh[(size_t)e1.x * 16 + sl];
        uint4 p2 = hh[(size_t)e2.x * 16 + sl];
        uint4 p3 = hh[(size_t)e3.x * 16 + sl];
        uint4 p4 = hh[(size_t)e4.x * 16 + sl];
        uint4 p5 = hh[(size_t)e5.x * 16 + sl];
        uint4 p6 = hh[(size_t)e6.x * 16 + sl];
        uint4 p7 = hh[(size_t)e7.x * 16 + sl];
        acc_edge16(l0, h0, p0, __int_as_float(e0.y));
        acc_edge16(l1, h1, p1, __int_as_float(e1.y));
        acc_edge16(l0, h0, p2, __int_as_float(e2.y));
        acc_edge16(l1, h1, p3, __int_as_float(e3.y));
        acc_edge16(l0, h0, p4, __int_as_float(e4.y));
        acc_edge16(l1, h1, p5, __int_as_float(e5.y));
        acc_edge16(l0, h0, p6, __int_as_float(e6.y));
        acc_edge16(l1, h1, p7, __int_as_float(e7.y));
    }
    for (; i + 2 <= end; i += 2) {
        int2 e0 = g_edge[i + 0];
        int2 e1 = g_edge[i + 1];
        uint4 p0 = hh[(size_t)e0.x * 16 + sl];
        uint4 p1 = hh[(size_t)e1.x * 16 + sl];
        acc_edge16(l0, h0, p0, __int_as_float(e0.y));
        acc_edge16(l1, h1, p1, __int_as_float(e1.y));
    }
    if (i < end) {
        int2 e0 = g_edge[i];
        uint4 p0 = hh[(size_t)e0.x * 16 + sl];
        acc_edge16(l0, h0, p0, __int_as_float(e0.y));
    }

    float4 lo = make_float4(l0.x + l1.x, l0.y + l1.y, l0.z + l1.z, l0.w + l1.w);
    float4 hi = make_float4(h0.x + h1.x, h0.y + h1.y, h0.z + h1.z, h0.w + h1.w);

    float* op = out + (size_t)grp * DIM + sl * 8;
    *reinterpret_cast<float4*>(op)     = lo;
    *reinterpret_cast<float4*>(op + 4) = hi;
}

// ---------------------------------------------------------------------------
extern "C" void kernel_launch(void* const* d_in, const int* in_sizes, int n_in,
                              void* d_out, int out_size) {
    const float* x    = (const float*)d_in[0];
    const float* W    = (const float*)d_in[1];
    const int*   erow = (const int*)  d_in[2];
    const int*   ecol = (const int*)  d_in[3];
    const float* eval = (const float*)d_in[4];
    float*       out  = (float*)d_out;

    int n_nodes = in_sizes[0] / DIM;
    int n_edges = in_sizes[2];

    static cudaStream_t s2 = nullptr;
    static cudaEvent_t  ev_fork = nullptr, ev_join = nullptr;
    if (!s2) {
        cudaStreamCreate(&s2);
        cudaEventCreateWithFlags(&ev_fork, cudaEventDisableTiming);
        cudaEventCreateWithFlags(&ev_join, cudaEventDisableTiming);
    }

    // Fork: GEMM branch on s2 (overlaps with LTS-bound binning chain)
    cudaEventRecord(ev_fork, 0);
    cudaStreamWaitEvent(s2, ev_fork, 0);
    k_prep_w<<<(DIM * DIM + 255) / 256, 256, 0, s2>>>(W);
    k_gemm<<<(n_nodes + 31) / 32, 256, 0, s2>>>(x);
    cudaEventRecord(ev_join, s2);

    // Binning chain on main stream (g_cnt pre-zeroed by previous call / BSS)
    {
        int e4 = n_edges >> 2;
        int nt = e4 + (n_edges - e4 * 4);
        k_hist<<<(nt + 255) / 256, 256>>>(erow, n_edges);
    }
    k_scan1<<<N_CHUNKS, SCAN_CHUNK>>>();
    k_scanC<<<N_CHUNKS, SCAN_CHUNK>>>(n_edges);
    {
        int e4 = n_edges >> 2;
        int nt = e4 + (n_edges - e4 * 4);
        k_place<<<(nt + 255) / 256, 256>>>(erow, ecol, eval, n_edges);
    }

    // Join: rowgather needs g_h (s2) and g_edge (main)
    cudaStreamWaitEvent(0, ev_join, 0);
    k_rowgather<<<(N_NODES + 7) / 8, 128>>>(out);
}

// round 16
// speedup vs baseline: 1.0829x; 1.0829x over previous
#include <cuda_runtime.h>
#include <cuda_bf16.h>
#include <cuda_fp16.h>

#define N_NODES 100000
#define DIM 128
#define MAX_EDGES 1700000
#define SCAN_CHUNK 512
#define N_CHUNKS ((N_NODES + SCAN_CHUNK - 1) / SCAN_CHUNK)   // 196

// ---------------------------------------------------------------------------
// Scratch (allocation-free rule: device globals)
// ---------------------------------------------------------------------------
__device__ __half g_h[N_NODES * DIM];         // h = x @ W^T  (fp16)
__device__ __half g_Wh[DIM * DIM];            // W in fp16
__device__ int    g_cnt[N_NODES];             // per-row count; self-restored to 0 by rowgather
__device__ int    g_rowstart[N_NODES + 1];    // CSR offsets
__device__ int    g_cursor[N_NODES];          // placement cursors
__device__ int    g_blocksum[N_CHUNKS];       // per-chunk totals
__device__ int2   g_edge[MAX_EDGES];          // (col, val-bits) grouped by row

// ---------------------------------------------------------------------------
__global__ void k_prep_w(const float* __restrict__ W) {
    int idx = blockIdx.x * blockDim.x + threadIdx.x;
    if (idx < DIM * DIM) g_Wh[idx] = __float2half_rn(W[idx]);
}

// ---------------------------------------------------------------------------
// GEMM via HMMA (proven; fully hidden under LTS-bound binning)
// ---------------------------------------------------------------------------
#define SSTRIDE 136

__global__ void __launch_bounds__(256) k_gemm(const float* __restrict__ x) {
    __shared__ __half sA[32 * SSTRIDE];
    __shared__ __half sB[DIM * SSTRIDE];

    const int tid  = threadIdx.x;
    const int row0 = blockIdx.x * 32;

    const uint4* w4 = reinterpret_cast<const uint4*>(g_Wh);
    #pragma unroll
    for (int i = tid; i < 2048; i += 256) {
        int r = i >> 4, cg = i & 15;
        *reinterpret_cast<uint4*>(&sB[r * SSTRIDE + cg * 8]) = w4[i];
    }
    const float4* x4 = reinterpret_cast<const float4*>(x + (size_t)row0 * DIM);
    #pragma unroll
    for (int i = tid; i < 1024; i += 256) {
        float4 v = x4[i];
        int r = i >> 5, k4 = i & 31;
        __half2 p0 = __floats2half2_rn(v.x, v.y);
        __half2 p1 = __floats2half2_rn(v.z, v.w);
        __half* d = &sA[r * SSTRIDE + k4 * 4];
        *reinterpret_cast<__half2*>(d)     = p0;
        *reinterpret_cast<__half2*>(d + 2) = p1;
    }
    __syncthreads();

    const int warp = tid >> 5, lane = tid & 31;
    const int wr = (warp & 1) * 16;
    const int wc = (warp >> 1) * 32;
    const int qr = lane >> 2, qc = lane & 3;

    float c[4][4];
    #pragma unroll
    for (int nc = 0; nc < 4; nc++)
        #pragma unroll
        for (int j = 0; j < 4; j++) c[nc][j] = 0.f;

    #pragma unroll
    for (int ks = 0; ks < 8; ks++) {
        const int k0 = ks * 16 + qc * 2;
        const __half* A0 = &sA[(wr + qr) * SSTRIDE + k0];
        const __half* A8 = A0 + 8 * SSTRIDE;
        unsigned a0 = *reinterpret_cast<const unsigned*>(A0);
        unsigned a1 = *reinterpret_cast<const unsigned*>(A8);
        unsigned a2 = *reinterpret_cast<const unsigned*>(A0 + 8);
        unsigned a3 = *reinterpret_cast<const unsigned*>(A8 + 8);
        #pragma unroll
        for (int nc = 0; nc < 4; nc++) {
            const int n = wc + nc * 8 + qr;
            const __half* B0 = &sB[n * SSTRIDE + k0];
            unsigned b0 = *reinterpret_cast<const unsigned*>(B0);
            unsigned b1 = *reinterpret_cast<const unsigned*>(B0 + 8);
            asm("mma.sync.aligned.m16n8k16.row.col.f32.f16.f16.f32 "
                "{%0,%1,%2,%3}, {%4,%5,%6,%7}, {%8,%9}, {%0,%1,%2,%3};"
                : "+f"(c[nc][0]), "+f"(c[nc][1]), "+f"(c[nc][2]), "+f"(c[nc][3])
                : "r"(a0), "r"(a1), "r"(a2), "r"(a3), "r"(b0), "r"(b1));
        }
    }

    const int r0g = row0 + wr + qr;
    #pragma unroll
    for (int nc = 0; nc < 4; nc++) {
        const int col = wc + nc * 8 + qc * 2;
        __half2 lo = __floats2half2_rn(c[nc][0], c[nc][1]);
        __half2 hi = __floats2half2_rn(c[nc][2], c[nc][3]);
        *reinterpret_cast<__half2*>(&g_h[(size_t)r0g * DIM + col])       = lo;
        *reinterpret_cast<__half2*>(&g_h[(size_t)(r0g + 8) * DIM + col]) = hi;
    }
}

// ---------------------------------------------------------------------------
// Phase 1: histogram of rows (L2-atomic bound; at floor).
// g_cnt arrives zeroed (BSS init on first call; rowgather restores it after).
// ---------------------------------------------------------------------------
__global__ void k_hist(const int* __restrict__ erow, int n_edges) {
    int t  = blockIdx.x * blockDim.x + threadIdx.x;
    int e4 = n_edges >> 2;
    if (t < e4) {
        int4 r = reinterpret_cast<const int4*>(erow)[t];
        atomicAdd(&g_cnt[r.x], 1);
        atomicAdd(&g_cnt[r.y], 1);
        atomicAdd(&g_cnt[r.z], 1);
        atomicAdd(&g_cnt[r.w], 1);
    } else {
        int e = e4 * 4 + (t - e4);
        if (e < n_edges) atomicAdd(&g_cnt[erow[e]], 1);
    }
}

// ---------------------------------------------------------------------------
// Phase 2a: per-chunk exclusive scan; writes per-chunk totals.
// ---------------------------------------------------------------------------
__global__ void __launch_bounds__(SCAN_CHUNK) k_scan1() {
    __shared__ int wsum[SCAN_CHUNK / 32];
    int tid  = threadIdx.x;
    int gidx = blockIdx.x * SCAN_CHUNK + tid;
    int v    = (gidx < N_NODES) ? g_cnt[gidx] : 0;

    int lane = tid & 31, wid = tid >> 5;
    int incl = v;
    #pragma unroll
    for (int d = 1; d < 32; d <<= 1) {
        int t = __shfl_up_sync(0xffffffff, incl, d);
        if (lane >= d) incl += t;
    }
    if (lane == 31) wsum[wid] = incl;
    __syncthreads();
    if (wid == 0) {
        int w = (lane < SCAN_CHUNK / 32) ? wsum[lane] : 0;
        int wi = w;
        #pragma unroll
        for (int d = 1; d < 32; d <<= 1) {
            int t = __shfl_up_sync(0xffffffff, wi, d);
            if (lane >= d) wi += t;
        }
        if (lane < SCAN_CHUNK / 32) wsum[lane] = wi - w;
    }
    __syncthreads();
    int excl = incl - v + wsum[wid];
    if (gidx < N_NODES) g_cnt[gidx] = excl;
    if (tid == SCAN_CHUNK - 1) g_blocksum[blockIdx.x] = excl + v;
}

// ---------------------------------------------------------------------------
// Phase 2b (merged scan2+scan3): warp 0 sums preceding chunk totals,
// then all threads write rowstart + cursor.
// ---------------------------------------------------------------------------
__global__ void __launch_bounds__(SCAN_CHUNK) k_scanC(int n_edges) {
    __shared__ int s_prefix;
    const int tid = threadIdx.x;
    const int bid = blockIdx.x;

    if (tid < 32) {
        int acc = 0;
        for (int j = tid; j < bid; j += 32) acc += g_blocksum[j];
        #pragma unroll
        for (int d = 16; d; d >>= 1)
            acc += __shfl_down_sync(0xffffffff, acc, d);
        if (tid == 0) s_prefix = acc;
    }
    __syncthreads();

    int gidx = bid * SCAN_CHUNK + tid;
    if (gidx < N_NODES) {
        int rs = g_cnt[gidx] + s_prefix;
        g_rowstart[gidx] = rs;
        g_cursor[gidx]   = rs;
    }
    if (gidx == N_NODES - 1) g_rowstart[N_NODES] = n_edges;
}

// Phase 3: place — 4 edges per thread, vectorized loads
__global__ void k_place(const int*   __restrict__ erow,
                        const int*   __restrict__ ecol,
                        const float* __restrict__ eval,
                        int n_edges) {
    int t  = blockIdx.x * blockDim.x + threadIdx.x;
    int e4 = n_edges >> 2;
    if (t < e4) {
        int4   r = reinterpret_cast<const int4*>(erow)[t];
        int4   c = reinterpret_cast<const int4*>(ecol)[t];
        float4 v = reinterpret_cast<const float4*>(eval)[t];
        int p0 = atomicAdd(&g_cursor[r.x], 1);
        int p1 = atomicAdd(&g_cursor[r.y], 1);
        int p2 = atomicAdd(&g_cursor[r.z], 1);
        int p3 = atomicAdd(&g_cursor[r.w], 1);
        g_edge[p0] = make_int2(c.x, __float_as_int(v.x));
        g_edge[p1] = make_int2(c.y, __float_as_int(v.y));
        g_edge[p2] = make_int2(c.z, __float_as_int(v.z));
        g_edge[p3] = make_int2(c.w, __float_as_int(v.w));
    } else {
        int e = e4 * 4 + (t - e4);
        if (e < n_edges) {
            int pos = atomicAdd(&g_cursor[erow[e]], 1);
            g_edge[pos] = make_int2(ecol[e], __float_as_int(eval[e]));
        }
    }
}

// ---------------------------------------------------------------------------
// Phase 4: rowgather + self-restoring counter zero.
// ---------------------------------------------------------------------------
__device__ __forceinline__ void acc_edge16(float4& aLo, float4& aHi, uint4 p, float v) {
    float2 f0 = __half22float2(*reinterpret_cast<__half2*>(&p.x));
    float2 f1 = __half22float2(*reinterpret_cast<__half2*>(&p.y));
    float2 f2 = __half22float2(*reinterpret_cast<__half2*>(&p.z));
    float2 f3 = __half22float2(*reinterpret_cast<__half2*>(&p.w));
    aLo.x += v * f0.x; aLo.y += v * f0.y; aLo.z += v * f1.x; aLo.w += v * f1.y;
    aHi.x += v * f2.x; aHi.y += v * f2.y; aHi.z += v * f3.x; aHi.w += v * f3.y;
}

__global__ void __launch_bounds__(128) k_rowgather(float* __restrict__ out) {
    int grp = blockIdx.x * 8 + (threadIdx.x >> 4);
    int sl  = threadIdx.x & 15;
    if (grp >= N_NODES) return;

    int beg = __ldg(&g_rowstart[grp]);
    int end = __ldg(&g_rowstart[grp + 1]);

    // Self-restore: leave g_cnt zeroed for the next graph replay's hist.
    if (sl == 0) g_cnt[grp] = 0;

    const uint4* hh = reinterpret_cast<const uint4*>(g_h);

    float4 l0 = make_float4(0.f,0.f,0.f,0.f), h0 = make_float4(0.f,0.f,0.f,0.f);
    float4 l1 = make_float4(0.f,0.f,0.f,0.f), h1 = make_float4(0.f,0.f,0.f,0.f);

    int i = beg;
    for (; i + 8 <= end; i += 8) {
        int2 e0 = g_edge[i + 0];
        int2 e1 = g_edge[i + 1];
        int2 e2 = g_edge[i + 2];
        int2 e3 = g_edge[i + 3];
        int2 e4 = g_edge[i + 4];
        int2 e5 = g_edge[i + 5];
        int2 e6 = g_edge[i + 6];
        int2 e7 = g_edge[i + 7];
        uint4 p0 = hh[(size_t)e0.x * 16 + sl];
        uint4 p1 = hh[(size_t)e1.x * 16 + sl];
        uint4 p2 = hh[(size_t)e2.x * 16 + sl];
        uint4 p3 = hh[(size_t)e3.x * 16 + sl];
        uint4 p4 = hh[(size_t)e4.x * 16 + sl];
        uint4 p5 = hh[(size_t)e5.x * 16 + sl];
        uint4 p6 = hh[(size_t)e6.x * 16 + sl];
        uint4 p7 = hh[(size_t)e7.x * 16 + sl];
        acc_edge16(l0, h0, p0, __int_as_float(e0.y));
        acc_edge16(l1, h1, p1, __int_as_float(e1.y));
        acc_edge16(l0, h0, p2, __int_as_float(e2.y));
        acc_edge16(l1, h1, p3, __int_as_float(e3.y));
        acc_edge16(l0, h0, p4, __int_as_float(e4.y));
        acc_edge16(l1, h1, p5, __int_as_float(e5.y));
        acc_edge16(l0, h0, p6, __int_as_float(e6.y));
        acc_edge16(l1, h1, p7, __int_as_float(e7.y));
    }
    for (; i + 2 <= end; i += 2) {
        int2 e0 = g_edge[i + 0];
        int2 e1 = g_edge[i + 1];
        uint4 p0 = hh[(size_t)e0.x * 16 + sl];
        uint4 p1 = hh[(size_t)e1.x * 16 + sl];
        acc_edge16(l0, h0, p0, __int_as_float(e0.y));
        acc_edge16(l1, h1, p1, __int_as_float(e1.y));
    }
    if (i < end) {
        int2 e0 = g_edge[i];
        uint4 p0 = hh[(size_t)e0.x * 16 + sl];
        acc_edge16(l0, h0, p0, __int_as_float(e0.y));
    }

    float4 lo = make_float4(l0.x + l1.x, l0.y + l1.y, l0.z + l1.z, l0.w + l1.w);
    float4 hi = make_float4(h0.x + h1.x, h0.y + h1.y, h0.z + h1.z, h0.w + h1.w);

    float* op = out + (size_t)grp * DIM + sl * 8;
    *reinterpret_cast<float4*>(op)     = lo;
    *reinterpret_cast<float4*>(op + 4) = hi;
}

// ---------------------------------------------------------------------------
extern "C" void kernel_launch(void* const* d_in, const int* in_sizes, int n_in,
                              void* d_out, int out_size) {
    const float* x    = (const float*)d_in[0];
    const float* W    = (const float*)d_in[1];
    const int*   erow = (const int*)  d_in[2];
    const int*   ecol = (const int*)  d_in[3];
    const float* eval = (const float*)d_in[4];
    float*       out  = (float*)d_out;

    int n_nodes = in_sizes[0] / DIM;
    int n_edges = in_sizes[2];

    static cudaStream_t s2 = nullptr;
    static cudaEvent_t  ev_fork = nullptr, ev_join = nullptr;
    if (!s2) {
        cudaStreamCreate(&s2);
        cudaEventCreateWithFlags(&ev_fork, cudaEventDisableTiming);
        cudaEventCreateWithFlags(&ev_join, cudaEventDisableTiming);
    }

    // Fork: GEMM branch on s2 (overlaps with LTS-bound binning chain)
    cudaEventRecord(ev_fork, 0);
    cudaStreamWaitEvent(s2, ev_fork, 0);
    k_prep_w<<<(DIM * DIM + 255) / 256, 256, 0, s2>>>(W);
    k_gemm<<<(n_nodes + 31) / 32, 256, 0, s2>>>(x);
    cudaEventRecord(ev_join, s2);

    // Binning chain on main stream (g_cnt pre-zeroed by previous call / BSS)
    {
        int e4 = n_edges >> 2;
        int nt = e4 + (n_edges - e4 * 4);
        k_hist<<<(nt + 255) / 256, 256>>>(erow, n_edges);
    }
    k_scan1<<<N_CHUNKS, SCAN_CHUNK>>>();
    k_scanC<<<N_CHUNKS, SCAN_CHUNK>>>(n_edges);
    {
        int e4 = n_edges >> 2;
        int nt = e4 + (n_edges - e4 * 4);
        k_place<<<(nt + 255) / 256, 256>>>(erow, ecol, eval, n_edges);
    }

    // Join: rowgather needs g_h (s2) and g_edge (main)
    cudaStreamWaitEvent(0, ev_join, 0);
    k_rowgather<<<(N_NODES + 7) / 8, 128>>>(out);
}

// round 17
// speedup vs baseline: 1.0986x; 1.0145x over previous
#include <cuda_runtime.h>
#include <cuda_bf16.h>
#include <cuda_fp16.h>

#define N_NODES 100000
#define DIM 128
#define MAX_EDGES 1700000
#define SCAN_CHUNK 512
#define N_CHUNKS ((N_NODES + SCAN_CHUNK - 1) / SCAN_CHUNK)   // 196

// ---------------------------------------------------------------------------
// Scratch (allocation-free rule: device globals)
// ---------------------------------------------------------------------------
__device__ __half g_h[N_NODES * DIM];         // h = x @ W^T  (fp16)
__device__ __half g_Wh[DIM * DIM];            // W in fp16
__device__ int    g_cnt[N_NODES];             // per-row count; self-restored to 0 by rowgather
__device__ int    g_rowstart[N_NODES + 1];    // CSR offsets
__device__ int    g_cursor[N_NODES];          // placement cursors
__device__ int    g_blocksum[N_CHUNKS];       // per-chunk totals
__device__ int2   g_edge[MAX_EDGES];          // (col, val-bits) grouped by row

// ---------------------------------------------------------------------------
__global__ void k_prep_w(const float* __restrict__ W) {
    int idx = blockIdx.x * blockDim.x + threadIdx.x;
    if (idx < DIM * DIM) g_Wh[idx] = __float2half_rn(W[idx]);
}

// ---------------------------------------------------------------------------
// GEMM via HMMA (proven; fully hidden under LTS-bound binning)
// ---------------------------------------------------------------------------
#define SSTRIDE 136

__global__ void __launch_bounds__(256) k_gemm(const float* __restrict__ x) {
    __shared__ __half sA[32 * SSTRIDE];
    __shared__ __half sB[DIM * SSTRIDE];

    const int tid  = threadIdx.x;
    const int row0 = blockIdx.x * 32;

    const uint4* w4 = reinterpret_cast<const uint4*>(g_Wh);
    #pragma unroll
    for (int i = tid; i < 2048; i += 256) {
        int r = i >> 4, cg = i & 15;
        *reinterpret_cast<uint4*>(&sB[r * SSTRIDE + cg * 8]) = w4[i];
    }
    const float4* x4 = reinterpret_cast<const float4*>(x + (size_t)row0 * DIM);
    #pragma unroll
    for (int i = tid; i < 1024; i += 256) {
        float4 v = x4[i];
        int r = i >> 5, k4 = i & 31;
        __half2 p0 = __floats2half2_rn(v.x, v.y);
        __half2 p1 = __floats2half2_rn(v.z, v.w);
        __half* d = &sA[r * SSTRIDE + k4 * 4];
        *reinterpret_cast<__half2*>(d)     = p0;
        *reinterpret_cast<__half2*>(d + 2) = p1;
    }
    __syncthreads();

    const int warp = tid >> 5, lane = tid & 31;
    const int wr = (warp & 1) * 16;
    const int wc = (warp >> 1) * 32;
    const int qr = lane >> 2, qc = lane & 3;

    float c[4][4];
    #pragma unroll
    for (int nc = 0; nc < 4; nc++)
        #pragma unroll
        for (int j = 0; j < 4; j++) c[nc][j] = 0.f;

    #pragma unroll
    for (int ks = 0; ks < 8; ks++) {
        const int k0 = ks * 16 + qc * 2;
        const __half* A0 = &sA[(wr + qr) * SSTRIDE + k0];
        const __half* A8 = A0 + 8 * SSTRIDE;
        unsigned a0 = *reinterpret_cast<const unsigned*>(A0);
        unsigned a1 = *reinterpret_cast<const unsigned*>(A8);
        unsigned a2 = *reinterpret_cast<const unsigned*>(A0 + 8);
        unsigned a3 = *reinterpret_cast<const unsigned*>(A8 + 8);
        #pragma unroll
        for (int nc = 0; nc < 4; nc++) {
            const int n = wc + nc * 8 + qr;
            const __half* B0 = &sB[n * SSTRIDE + k0];
            unsigned b0 = *reinterpret_cast<const unsigned*>(B0);
            unsigned b1 = *reinterpret_cast<const unsigned*>(B0 + 8);
            asm("mma.sync.aligned.m16n8k16.row.col.f32.f16.f16.f32 "
                "{%0,%1,%2,%3}, {%4,%5,%6,%7}, {%8,%9}, {%0,%1,%2,%3};"
                : "+f"(c[nc][0]), "+f"(c[nc][1]), "+f"(c[nc][2]), "+f"(c[nc][3])
                : "r"(a0), "r"(a1), "r"(a2), "r"(a3), "r"(b0), "r"(b1));
        }
    }

    const int r0g = row0 + wr + qr;
    #pragma unroll
    for (int nc = 0; nc < 4; nc++) {
        const int col = wc + nc * 8 + qc * 2;
        __half2 lo = __floats2half2_rn(c[nc][0], c[nc][1]);
        __half2 hi = __floats2half2_rn(c[nc][2], c[nc][3]);
        *reinterpret_cast<__half2*>(&g_h[(size_t)r0g * DIM + col])       = lo;
        *reinterpret_cast<__half2*>(&g_h[(size_t)(r0g + 8) * DIM + col]) = hi;
    }
}

// ---------------------------------------------------------------------------
// Phase 1: histogram of rows (L2-atomic bound; at floor).
// g_cnt arrives zeroed (BSS init on first call; rowgather restores it after).
// ---------------------------------------------------------------------------
__global__ void k_hist(const int* __restrict__ erow, int n_edges) {
    int t  = blockIdx.x * blockDim.x + threadIdx.x;
    int e4 = n_edges >> 2;
    if (t < e4) {
        int4 r = reinterpret_cast<const int4*>(erow)[t];
        atomicAdd(&g_cnt[r.x], 1);
        atomicAdd(&g_cnt[r.y], 1);
        atomicAdd(&g_cnt[r.z], 1);
        atomicAdd(&g_cnt[r.w], 1);
    } else {
        int e = e4 * 4 + (t - e4);
        if (e < n_edges) atomicAdd(&g_cnt[erow[e]], 1);
    }
}

// ---------------------------------------------------------------------------
// Phase 2a: per-chunk exclusive scan; writes per-chunk totals.
// ---------------------------------------------------------------------------
__global__ void __launch_bounds__(SCAN_CHUNK) k_scan1() {
    __shared__ int wsum[SCAN_CHUNK / 32];
    int tid  = threadIdx.x;
    int gidx = blockIdx.x * SCAN_CHUNK + tid;
    int v    = (gidx < N_NODES) ? g_cnt[gidx] : 0;

    int lane = tid & 31, wid = tid >> 5;
    int incl = v;
    #pragma unroll
    for (int d = 1; d < 32; d <<= 1) {
        int t = __shfl_up_sync(0xffffffff, incl, d);
        if (lane >= d) incl += t;
    }
    if (lane == 31) wsum[wid] = incl;
    __syncthreads();
    if (wid == 0) {
        int w = (lane < SCAN_CHUNK / 32) ? wsum[lane] : 0;
        int wi = w;
        #pragma unroll
        for (int d = 1; d < 32; d <<= 1) {
            int t = __shfl_up_sync(0xffffffff, wi, d);
            if (lane >= d) wi += t;
        }
        if (lane < SCAN_CHUNK / 32) wsum[lane] = wi - w;
    }
    __syncthreads();
    int excl = incl - v + wsum[wid];
    if (gidx < N_NODES) g_cnt[gidx] = excl;
    if (tid == SCAN_CHUNK - 1) g_blocksum[blockIdx.x] = excl + v;
}

// ---------------------------------------------------------------------------
// Phase 2b (merged scan2+scan3): warp 0 sums preceding chunk totals,
// then all threads write rowstart + cursor.
// ---------------------------------------------------------------------------
__global__ void __launch_bounds__(SCAN_CHUNK) k_scanC(int n_edges) {
    __shared__ int s_prefix;
    const int tid = threadIdx.x;
    const int bid = blockIdx.x;

    if (tid < 32) {
        int acc = 0;
        for (int j = tid; j < bid; j += 32) acc += g_blocksum[j];
        #pragma unroll
        for (int d = 16; d; d >>= 1)
            acc += __shfl_down_sync(0xffffffff, acc, d);
        if (tid == 0) s_prefix = acc;
    }
    __syncthreads();

    int gidx = bid * SCAN_CHUNK + tid;
    if (gidx < N_NODES) {
        int rs = g_cnt[gidx] + s_prefix;
        g_rowstart[gidx] = rs;
        g_cursor[gidx]   = rs;
    }
    if (gidx == N_NODES - 1) g_rowstart[N_NODES] = n_edges;
}

// Phase 3: place — 4 edges per thread, vectorized loads
__global__ void k_place(const int*   __restrict__ erow,
                        const int*   __restrict__ ecol,
                        const float* __restrict__ eval,
                        int n_edges) {
    int t  = blockIdx.x * blockDim.x + threadIdx.x;
    int e4 = n_edges >> 2;
    if (t < e4) {
        int4   r = reinterpret_cast<const int4*>(erow)[t];
        int4   c = reinterpret_cast<const int4*>(ecol)[t];
        float4 v = reinterpret_cast<const float4*>(eval)[t];
        int p0 = atomicAdd(&g_cursor[r.x], 1);
        int p1 = atomicAdd(&g_cursor[r.y], 1);
        int p2 = atomicAdd(&g_cursor[r.z], 1);
        int p3 = atomicAdd(&g_cursor[r.w], 1);
        g_edge[p0] = make_int2(c.x, __float_as_int(v.x));
        g_edge[p1] = make_int2(c.y, __float_as_int(v.y));
        g_edge[p2] = make_int2(c.z, __float_as_int(v.z));
        g_edge[p3] = make_int2(c.w, __float_as_int(v.w));
    } else {
        int e = e4 * 4 + (t - e4);
        if (e < n_edges) {
            int pos = atomicAdd(&g_cursor[erow[e]], 1);
            g_edge[pos] = make_int2(ecol[e], __float_as_int(eval[e]));
        }
    }
}

// ---------------------------------------------------------------------------
// Phase 4: rowgather + self-restoring counter zero.
// Edge metadata read as aligned int4 (2 edges per LDG.128 broadcast).
// ---------------------------------------------------------------------------
__device__ __forceinline__ void acc_edge16(float4& aLo, float4& aHi, uint4 p, float v) {
    float2 f0 = __half22float2(*reinterpret_cast<__half2*>(&p.x));
    float2 f1 = __half22float2(*reinterpret_cast<__half2*>(&p.y));
    float2 f2 = __half22float2(*reinterpret_cast<__half2*>(&p.z));
    float2 f3 = __half22float2(*reinterpret_cast<__half2*>(&p.w));
    aLo.x += v * f0.x; aLo.y += v * f0.y; aLo.z += v * f1.x; aLo.w += v * f1.y;
    aHi.x += v * f2.x; aHi.y += v * f2.y; aHi.z += v * f3.x; aHi.w += v * f3.y;
}

__global__ void __launch_bounds__(128) k_rowgather(float* __restrict__ out) {
    int grp = blockIdx.x * 8 + (threadIdx.x >> 4);
    int sl  = threadIdx.x & 15;
    if (grp >= N_NODES) return;

    int beg = __ldg(&g_rowstart[grp]);
    int end = __ldg(&g_rowstart[grp + 1]);

    // Self-restore: leave g_cnt zeroed for the next graph replay's hist.
    if (sl == 0) g_cnt[grp] = 0;

    const uint4* hh = reinterpret_cast<const uint4*>(g_h);

    float4 l0 = make_float4(0.f,0.f,0.f,0.f), h0 = make_float4(0.f,0.f,0.f,0.f);
    float4 l1 = make_float4(0.f,0.f,0.f,0.f), h1 = make_float4(0.f,0.f,0.f,0.f);

    int i = beg;
    // Peel one edge if beg is odd -> i becomes even -> int4-aligned edge pairs
    if (i < end && (i & 1)) {
        int2 e0 = g_edge[i];
        uint4 p0 = hh[(size_t)e0.x * 16 + sl];
        acc_edge16(l0, h0, p0, __int_as_float(e0.y));
        i++;
    }

    const int4* ep4 = reinterpret_cast<const int4*>(g_edge);   // 2 edges per int4

    for (; i + 8 <= end; i += 8) {
        int half = i >> 1;
        int4 q0 = ep4[half + 0];   // edges i,   i+1 : {col0,val0,col1,val1}
        int4 q1 = ep4[half + 1];   // edges i+2, i+3
        int4 q2 = ep4[half + 2];   // edges i+4, i+5
        int4 q3 = ep4[half + 3];   // edges i+6, i+7
        uint4 p0 = hh[(size_t)q0.x * 16 + sl];
        uint4 p1 = hh[(size_t)q0.z * 16 + sl];
        uint4 p2 = hh[(size_t)q1.x * 16 + sl];
        uint4 p3 = hh[(size_t)q1.z * 16 + sl];
        uint4 p4 = hh[(size_t)q2.x * 16 + sl];
        uint4 p5 = hh[(size_t)q2.z * 16 + sl];
        uint4 p6 = hh[(size_t)q3.x * 16 + sl];
        uint4 p7 = hh[(size_t)q3.z * 16 + sl];
        acc_edge16(l0, h0, p0, __int_as_float(q0.y));
        acc_edge16(l1, h1, p1, __int_as_float(q0.w));
        acc_edge16(l0, h0, p2, __int_as_float(q1.y));
        acc_edge16(l1, h1, p3, __int_as_float(q1.w));
        acc_edge16(l0, h0, p4, __int_as_float(q2.y));
        acc_edge16(l1, h1, p5, __int_as_float(q2.w));
        acc_edge16(l0, h0, p6, __int_as_float(q3.y));
        acc_edge16(l1, h1, p7, __int_as_float(q3.w));
    }
    for (; i + 2 <= end; i += 2) {
        int4 q0 = ep4[i >> 1];
        uint4 p0 = hh[(size_t)q0.x * 16 + sl];
        uint4 p1 = hh[(size_t)q0.z * 16 + sl];
        acc_edge16(l0, h0, p0, __int_as_float(q0.y));
        acc_edge16(l1, h1, p1, __int_as_float(q0.w));
    }
    if (i < end) {
        int2 e0 = g_edge[i];
        uint4 p0 = hh[(size_t)e0.x * 16 + sl];
        acc_edge16(l0, h0, p0, __int_as_float(e0.y));
    }

    float4 lo = make_float4(l0.x + l1.x, l0.y + l1.y, l0.z + l1.z, l0.w + l1.w);
    float4 hi = make_float4(h0.x + h1.x, h0.y + h1.y, h0.z + h1.z, h0.w + h1.w);

    float* op = out + (size_t)grp * DIM + sl * 8;
    *reinterpret_cast<float4*>(op)     = lo;
    *reinterpret_cast<float4*>(op + 4) = hi;
}

// ---------------------------------------------------------------------------
extern "C" void kernel_launch(void* const* d_in, const int* in_sizes, int n_in,
                              void* d_out, int out_size) {
    const float* x    = (const float*)d_in[0];
    const float* W    = (const float*)d_in[1];
    const int*   erow = (const int*)  d_in[2];
    const int*   ecol = (const int*)  d_in[3];
    const float* eval = (const float*)d_in[4];
    float*       out  = (float*)d_out;

    int n_nodes = in_sizes[0] / DIM;
    int n_edges = in_sizes[2];

    static cudaStream_t s2 = nullptr;
    static cudaEvent_t  ev_fork = nullptr, ev_join = nullptr;
    if (!s2) {
        cudaStreamCreate(&s2);
        cudaEventCreateWithFlags(&ev_fork, cudaEventDisableTiming);
        cudaEventCreateWithFlags(&ev_join, cudaEventDisableTiming);
    }

    // Fork: GEMM branch on s2 (overlaps with LTS-bound binning chain)
    cudaEventRecord(ev_fork, 0);
    cudaStreamWaitEvent(s2, ev_fork, 0);
    k_prep_w<<<(DIM * DIM + 255) / 256, 256, 0, s2>>>(W);
    k_gemm<<<(n_nodes + 31) / 32, 256, 0, s2>>>(x);
    cudaEventRecord(ev_join, s2);

    // Binning chain on main stream (g_cnt pre-zeroed by previous call / BSS)
    {
        int e4 = n_edges >> 2;
        int nt = e4 + (n_edges - e4 * 4);
        k_hist<<<(nt + 255) / 256, 256>>>(erow, n_edges);
    }
    k_scan1<<<N_CHUNKS, SCAN_CHUNK>>>();
    k_scanC<<<N_CHUNKS, SCAN_CHUNK>>>(n_edges);
    {
        int e4 = n_edges >> 2;
        int nt = e4 + (n_edges - e4 * 4);
        k_place<<<(nt + 255) / 256, 256>>>(erow, ecol, eval, n_edges);
    }

    // Join: rowgather needs g_h (s2) and g_edge (main)
    cudaStreamWaitEvent(0, ev_join, 0);
    k_rowgather<<<(N_NODES + 7) / 8, 128>>>(out);
}